// round 6
// baseline (speedup 1.0000x reference)
#include <cuda_runtime.h>
#include <cstdint>

#define NN     100000
#define EE     1000000
#define DIN    128
#define DOUT   64
#define DEDGE  11
#define ET     (EE + NN)

// ---------------- scratch (device globals) ----------------------------------
__device__ float g_xl[NN * DOUT];          // x @ W_l   (25.6 MB)
__device__ float g_xr[NN * DOUT];          // x @ W_r   (25.6 MB)
__device__ float g_ex[ET];                 // per-edge exp(logit) (4.4 MB)
__device__ float4 g_la4[NN * 3];           // padded loop-attr rows: 12 floats
                                           // slots 0..10 = attr sums, 11 = deg
__device__ float g_denom[NN];

// ---------------- 0: init ---------------------------------------------------
__global__ void k_init(float* __restrict__ out) {
    int i = blockIdx.x * blockDim.x + threadIdx.x;
    if (i < NN) g_denom[i] = 0.0f;
    if (i < NN * 3) g_la4[i] = make_float4(0.f, 0.f, 0.f, 0.f);
    if (i < NN * DOUT) out[i] = 0.0f;
}

// ---------------- 1: degree + incoming-attr sums (3x v4 red per edge) --------
__global__ void k_deg(const int* __restrict__ ei, const float* __restrict__ ea) {
    int e = blockIdx.x * blockDim.x + threadIdx.x;
    if (e >= EE) return;
    int dst = __ldg(&ei[EE + e]);
    const float* a = ea + (size_t)e * DEDGE;
    float v[12];
#pragma unroll
    for (int k = 0; k < DEDGE; k++) v[k] = __ldg(&a[k]);
    v[11] = 1.0f;  // degree count packed in slot 11
    float* base = (float*)(g_la4 + (size_t)dst * 3);
#pragma unroll
    for (int q = 0; q < 3; q++) {
        unsigned long long gp =
            (unsigned long long)__cvta_generic_to_global(base + 4 * q);
        asm volatile("red.global.add.v4.f32 [%0], {%1,%2,%3,%4};"
                     :: "l"(gp), "f"(v[4*q]), "f"(v[4*q+1]),
                        "f"(v[4*q+2]), "f"(v[4*q+3])
                     : "memory");
    }
}

// ---------------- 2: normalize loop attrs (mean) -----------------------------
__global__ void k_norm() {
    int i = blockIdx.x * blockDim.x + threadIdx.x;
    if (i >= NN) return;
    float* row = (float*)(g_la4 + (size_t)i * 3);
    float inv = 1.0f / fmaxf(row[11], 1.0f);
#pragma unroll
    for (int k = 0; k < DEDGE; k++) row[k] *= inv;
}

// ---------------- 3: tensor-core dual GEMM (3xTF32 error-compensated) --------
// Block: 256 thr = 8 warps, M-tile 128 rows, N=64, K=128.
// Warps 0-3 compute xl (Wl), warps 4-7 compute xr (Wr); 32 rows per warp
// as two m16 halves. mma.sync.m16n8k8 tf32, D accumulated fp32.
// 3xTF32: A=Ah+Al, B=Bh+Bl; D += AhBh + AlBh + AhBl (residual ~2^-22).
// smem strides chosen conflict-free: x stride 132, W stride 72.
#define SXS   132
#define SWS   72
#define SM_X  0
#define SM_WHL (SM_X  + 128 * SXS)          // 16896
#define SM_WLL (SM_WHL + 128 * SWS)         // 26112
#define SM_WHR (SM_WLL + 128 * SWS)         // 35328
#define SM_WLR (SM_WHR + 128 * SWS)         // 44544
#define SM_TOT_F (SM_WLR + 128 * SWS)       // 53760 floats = 215040 B

__device__ __forceinline__ unsigned f2tf(float f) {
    unsigned u;
    asm("cvt.rna.tf32.f32 %0, %1;" : "=r"(u) : "f"(f));
    return u;
}
__device__ __forceinline__ void mma_tf32(float* d, unsigned a0, unsigned a1,
                                         unsigned a2, unsigned a3,
                                         unsigned b0, unsigned b1) {
    asm volatile(
        "mma.sync.aligned.m16n8k8.row.col.f32.tf32.tf32.f32 "
        "{%0,%1,%2,%3}, {%4,%5,%6,%7}, {%8,%9}, {%0,%1,%2,%3};"
        : "+f"(d[0]), "+f"(d[1]), "+f"(d[2]), "+f"(d[3])
        : "r"(a0), "r"(a1), "r"(a2), "r"(a3), "r"(b0), "r"(b1));
}

__global__ void __launch_bounds__(256, 1)
k_gemm(const float* __restrict__ x, const float* __restrict__ Wl,
       const float* __restrict__ Wr) {
    extern __shared__ float sm[];
    float* sx = sm + SM_X;

    int tid  = threadIdx.x;
    int warp = tid >> 5;
    int lane = tid & 31;
    int grp  = lane >> 2;   // 0..7
    int ctid = lane & 3;    // 0..3

    // --- convert W -> tf32 hi/lo in smem (once per block) ---
    for (int i = tid; i < DIN * DOUT; i += 256) {
        int k = i >> 6, n = i & 63;
        float f = __ldg(&Wl[i]);
        unsigned h = f2tf(f);
        sm[SM_WHL + k * SWS + n] = __uint_as_float(h);
        sm[SM_WLL + k * SWS + n] = __uint_as_float(f2tf(f - __uint_as_float(h)));
        f = __ldg(&Wr[i]);
        h = f2tf(f);
        sm[SM_WHR + k * SWS + n] = __uint_as_float(h);
        sm[SM_WLR + k * SWS + n] = __uint_as_float(f2tf(f - __uint_as_float(h)));
    }

    // --- load x tile 128 x 128 (zero-pad OOB rows) ---
    int row0 = blockIdx.x * 128;
    {
        const float4* xg = (const float4*)x;
        for (int i = tid; i < 128 * 32; i += 256) {
            int r = i >> 5, c4 = i & 31;
            float4 v = make_float4(0.f, 0.f, 0.f, 0.f);
            if (row0 + r < NN) v = xg[(size_t)(row0 + r) * 32 + c4];
            *(float4*)&sx[r * SXS + c4 * 4] = v;
        }
    }
    __syncthreads();

    bool isR = warp >= 4;
    int  w   = warp & 3;
    const float* sWh = sm + (isR ? SM_WHR : SM_WHL);
    const float* sWlo = sm + (isR ? SM_WLR : SM_WLL);
    float* gout = isR ? g_xr : g_xl;
    int wr0 = w * 32;   // warp's first row within tile

    float d[2][8][4];
#pragma unroll
    for (int h = 0; h < 2; h++)
#pragma unroll
        for (int t = 0; t < 8; t++)
#pragma unroll
            for (int q = 0; q < 4; q++) d[h][t][q] = 0.f;

#pragma unroll 1
    for (int k0 = 0; k0 < DIN; k0 += 8) {
        // B fragments for all 8 n-tiles (hi and lo)
        unsigned bh[8][2], bl[8][2];
        const float* ph0 = sWh  + (k0 + ctid) * SWS + grp;
        const float* ph1 = sWh  + (k0 + ctid + 4) * SWS + grp;
        const float* pl0 = sWlo + (k0 + ctid) * SWS + grp;
        const float* pl1 = sWlo + (k0 + ctid + 4) * SWS + grp;
#pragma unroll
        for (int t = 0; t < 8; t++) {
            bh[t][0] = __float_as_uint(ph0[8 * t]);
            bh[t][1] = __float_as_uint(ph1[8 * t]);
            bl[t][0] = __float_as_uint(pl0[8 * t]);
            bl[t][1] = __float_as_uint(pl1[8 * t]);
        }
#pragma unroll
        for (int h = 0; h < 2; h++) {
            int rb = wr0 + 16 * h;
            float f0 = sx[(rb + grp)     * SXS + k0 + ctid];
            float f1 = sx[(rb + grp + 8) * SXS + k0 + ctid];
            float f2 = sx[(rb + grp)     * SXS + k0 + ctid + 4];
            float f3 = sx[(rb + grp + 8) * SXS + k0 + ctid + 4];
            unsigned a0 = f2tf(f0), a1 = f2tf(f1), a2 = f2tf(f2), a3 = f2tf(f3);
            unsigned l0 = f2tf(f0 - __uint_as_float(a0));
            unsigned l1 = f2tf(f1 - __uint_as_float(a1));
            unsigned l2 = f2tf(f2 - __uint_as_float(a2));
            unsigned l3 = f2tf(f3 - __uint_as_float(a3));
#pragma unroll
            for (int t = 0; t < 8; t++) {
                mma_tf32(d[h][t], a0, a1, a2, a3, bh[t][0], bh[t][1]);
                mma_tf32(d[h][t], l0, l1, l2, l3, bh[t][0], bh[t][1]);
                mma_tf32(d[h][t], a0, a1, a2, a3, bl[t][0], bl[t][1]);
            }
        }
    }

    // --- store D ---
#pragma unroll
    for (int h = 0; h < 2; h++) {
        int rb = row0 + wr0 + 16 * h;
#pragma unroll
        for (int t = 0; t < 8; t++) {
            int col = 8 * t + 2 * ctid;
            int r0 = rb + grp;
            int r1 = rb + grp + 8;
            if (r0 < NN)
                *(float2*)&gout[(size_t)r0 * DOUT + col] =
                    make_float2(d[h][t][0], d[h][t][1]);
            if (r1 < NN)
                *(float2*)&gout[(size_t)r1 * DOUT + col] =
                    make_float2(d[h][t][2], d[h][t][3]);
        }
    }
}

// ---------------- 4: per-edge logit -> exp -> denom --------------------------
// One warp per edge. No segment-max (validated safe in fp32).
__global__ void __launch_bounds__(256)
k_logits(const int* __restrict__ ei, const float* __restrict__ ea,
         const float* __restrict__ We, const float* __restrict__ att) {
    __shared__ float sWe[DEDGE * DOUT];   // row-major, read as float2
    __shared__ float sAtt[DOUT];
    for (int i = threadIdx.x; i < DEDGE * DOUT; i += 256) sWe[i] = We[i];
    if (threadIdx.x < DOUT) sAtt[threadIdx.x] = att[threadIdx.x];
    __syncthreads();

    int widx = (int)((blockIdx.x * blockDim.x + threadIdx.x) >> 5);
    int lane = threadIdx.x & 31;
    if (widx >= ET) return;

    int src, dst;
    const float* a;
    if (widx < EE) {
        src = __ldg(&ei[widx]);
        dst = __ldg(&ei[EE + widx]);
        a = ea + (size_t)widx * DEDGE;
    } else {
        src = dst = widx - EE;
        a = (const float*)(g_la4 + (size_t)(widx - EE) * 3);
    }

    float av = (lane < DEDGE) ? a[lane] : 0.0f;

    const float2* sWe2 = (const float2*)sWe;
    float e0 = 0.0f, e1 = 0.0f;
#pragma unroll
    for (int k = 0; k < DEDGE; k++) {
        float ak = __shfl_sync(0xFFFFFFFFu, av, k);
        float2 w = sWe2[k * 32 + lane];
        e0 = fmaf(ak, w.x, e0);
        e1 = fmaf(ak, w.y, e1);
    }

    float2 xlv = ((const float2*)g_xl)[(size_t)src * 32 + lane];
    float2 xrv = ((const float2*)g_xr)[(size_t)dst * 32 + lane];
    float m0 = xlv.x + xrv.x + e0;  m0 = (m0 >= 0.0f) ? m0 : 0.2f * m0;
    float m1 = xlv.y + xrv.y + e1;  m1 = (m1 >= 0.0f) ? m1 : 0.2f * m1;

    const float2* sAtt2 = (const float2*)sAtt;
    float2 at = sAtt2[lane];
    float v = m0 * at.x + m1 * at.y;
#pragma unroll
    for (int o = 16; o > 0; o >>= 1) v += __shfl_xor_sync(0xFFFFFFFFu, v, o);

    if (lane == 0) {
        float ex = __expf(v);            // no max subtraction needed
        g_ex[widx] = ex;
        atomicAdd(&g_denom[dst], ex);
    }
}

// ---------------- 5: weighted scatter (half-warp per edge) -------------------
__global__ void __launch_bounds__(256)
k_accum(const int* __restrict__ ei, float* __restrict__ out) {
    int h = (int)((blockIdx.x * blockDim.x + threadIdx.x) >> 4);  // edge idx
    int c = threadIdx.x & 15;                                      // chunk 0..15
    if (h >= ET) return;

    int src, dst;
    if (h < EE) {
        src = __ldg(&ei[h]);
        dst = __ldg(&ei[EE + h]);
    } else {
        src = dst = h - EE;
    }

    float ex = __ldg(&g_ex[h]);
    float4 xlv = ((const float4*)g_xl)[(size_t)src * 16 + c];
    float4 w;
    w.x = ex * xlv.x; w.y = ex * xlv.y; w.z = ex * xlv.z; w.w = ex * xlv.w;
    float* p = out + (size_t)dst * DOUT + c * 4;
    unsigned long long gp = (unsigned long long)__cvta_generic_to_global(p);
    asm volatile("red.global.add.v4.f32 [%0], {%1,%2,%3,%4};"
                 :: "l"(gp), "f"(w.x), "f"(w.y), "f"(w.z), "f"(w.w)
                 : "memory");
}

// ---------------- 6: final divide by softmax denominator ---------------------
__global__ void k_final(float* __restrict__ out) {
    int i = blockIdx.x * blockDim.x + threadIdx.x;
    if (i >= NN * DOUT) return;
    out[i] = out[i] / g_denom[i >> 6];
}

// ---------------- launch -----------------------------------------------------
extern "C" void kernel_launch(void* const* d_in, const int* in_sizes, int n_in,
                              void* d_out, int out_size) {
    const float* x   = (const float*)d_in[0];
    const int*   ei  = (const int*)  d_in[1];
    const float* ea  = (const float*)d_in[2];
    const float* Wl  = (const float*)d_in[3];
    const float* Wr  = (const float*)d_in[4];
    const float* We  = (const float*)d_in[5];
    const float* att = (const float*)d_in[6];
    float* out = (float*)d_out;

    cudaFuncSetAttribute(k_gemm, cudaFuncAttributeMaxDynamicSharedMemorySize,
                         SM_TOT_F * 4);

    k_init  <<<(NN * DOUT + 255) / 256, 256>>>(out);
    k_deg   <<<(EE + 255) / 256, 256>>>(ei, ea);
    k_norm  <<<(NN + 255) / 256, 256>>>();
    k_gemm  <<<(NN + 127) / 128, 256, SM_TOT_F * 4>>>(x, Wl, Wr);
    k_logits<<<(ET * 32 + 255) / 256, 256>>>(ei, ea, We, att);
    k_accum <<<(ET * 16 + 255) / 256, 256>>>(ei, out);
    k_final <<<(NN * DOUT + 255) / 256, 256>>>(out);
}

// round 8
// speedup vs baseline: 1.2295x; 1.2295x over previous
#include <cuda_runtime.h>
#include <cstdint>

#define NN     100000
#define EE     1000000
#define DIN    128
#define DOUT   64
#define DEDGE  11
#define ET     (EE + NN)

// ---------------- scratch (device globals) ----------------------------------
__device__ float g_xl[NN * DOUT];          // x @ W_l   (25.6 MB)
__device__ float g_xr[NN * DOUT];          // x @ W_r   (25.6 MB)
__device__ float4 g_la4[NN * 3];           // padded loop-attr rows: 12 floats
                                           // slots 0..10 = attr sums, 11 = deg
__device__ float g_denom[NN];

// ---------------- 0: init ---------------------------------------------------
__global__ void k_init(float* __restrict__ out) {
    int i = blockIdx.x * blockDim.x + threadIdx.x;
    if (i < NN) g_denom[i] = 0.0f;
    if (i < NN * 3) g_la4[i] = make_float4(0.f, 0.f, 0.f, 0.f);
    if (i < NN * DOUT) out[i] = 0.0f;
}

// ---------------- 1: degree + incoming-attr sums (3x v4 red per edge) --------
__global__ void k_deg(const int* __restrict__ ei, const float* __restrict__ ea) {
    int e = blockIdx.x * blockDim.x + threadIdx.x;
    if (e >= EE) return;
    int dst = __ldg(&ei[EE + e]);
    const float* a = ea + (size_t)e * DEDGE;
    float v[12];
#pragma unroll
    for (int k = 0; k < DEDGE; k++) v[k] = __ldg(&a[k]);
    v[11] = 1.0f;  // degree count packed in slot 11
    float* base = (float*)(g_la4 + (size_t)dst * 3);
#pragma unroll
    for (int q = 0; q < 3; q++) {
        unsigned long long gp =
            (unsigned long long)__cvta_generic_to_global(base + 4 * q);
        asm volatile("red.global.add.v4.f32 [%0], {%1,%2,%3,%4};"
                     :: "l"(gp), "f"(v[4*q]), "f"(v[4*q+1]),
                        "f"(v[4*q+2]), "f"(v[4*q+3])
                     : "memory");
    }
}

// ---------------- 2: normalize loop attrs (mean) -----------------------------
__global__ void k_norm() {
    int i = blockIdx.x * blockDim.x + threadIdx.x;
    if (i >= NN) return;
    float* row = (float*)(g_la4 + (size_t)i * 3);
    float inv = 1.0f / fmaxf(row[11], 1.0f);
#pragma unroll
    for (int k = 0; k < DEDGE; k++) row[k] *= inv;
}

// ---------------- 3: tensor-core dual GEMM (3xTF32), occupancy-tuned ---------
// Block: 256 thr = 8 warps, M-tile 64 rows, N=64, K=128.
// Warps 0-3: Wl, warps 4-7: Wr; each warp one m16 slab (16 rows), 8 n-tiles.
// W kept in smem as raw fp32 (cheap fill); tf32 hi/lo split happens at
// fragment load on the idle alu/fma pipes.
// smem: x 64x132 (33.8KB) + Wl 128x72 + Wr 128x72 (73.7KB) = 107.5KB
//   -> 2 CTAs/SM.
#define SXS   132
#define SWS   72
#define SM_X   0
#define SM_WL  (SM_X + 64 * SXS)            // 8448
#define SM_WR  (SM_WL + 128 * SWS)          // 17664
#define SM_TOT_F (SM_WR + 128 * SWS)        // 26880 floats = 107520 B
#define TILE_M 64

__device__ __forceinline__ unsigned f2tf(float f) {
    unsigned u;
    asm("cvt.rna.tf32.f32 %0, %1;" : "=r"(u) : "f"(f));
    return u;
}
__device__ __forceinline__ void mma_tf32(float* d, unsigned a0, unsigned a1,
                                         unsigned a2, unsigned a3,
                                         unsigned b0, unsigned b1) {
    asm volatile(
        "mma.sync.aligned.m16n8k8.row.col.f32.tf32.tf32.f32 "
        "{%0,%1,%2,%3}, {%4,%5,%6,%7}, {%8,%9}, {%0,%1,%2,%3};"
        : "+f"(d[0]), "+f"(d[1]), "+f"(d[2]), "+f"(d[3])
        : "r"(a0), "r"(a1), "r"(a2), "r"(a3), "r"(b0), "r"(b1));
}

__global__ void __launch_bounds__(256, 2)
k_gemm(const float* __restrict__ x, const float* __restrict__ Wl,
       const float* __restrict__ Wr) {
    extern __shared__ float sm[];
    float* sx = sm + SM_X;

    int tid  = threadIdx.x;
    int warp = tid >> 5;
    int lane = tid & 31;
    int grp  = lane >> 2;   // 0..7
    int ctid = lane & 3;    // 0..3

    // --- fill W (plain fp32 copy, stride 72) ---
    for (int i = tid; i < (DIN * DOUT) / 4; i += 256) {
        int k = i >> 4, n4 = i & 15;               // n4: group of 4 cols
        float4 vl = __ldg((const float4*)Wl + i);
        float4 vr = __ldg((const float4*)Wr + i);
        *(float4*)&sm[SM_WL + k * SWS + n4 * 4] = vl;
        *(float4*)&sm[SM_WR + k * SWS + n4 * 4] = vr;
    }

    // --- load x tile 64 x 128 (zero-pad OOB rows) ---
    int row0 = blockIdx.x * TILE_M;
    {
        const float4* xg = (const float4*)x;
        for (int i = tid; i < TILE_M * 32; i += 256) {
            int r = i >> 5, c4 = i & 31;
            float4 v = make_float4(0.f, 0.f, 0.f, 0.f);
            if (row0 + r < NN) v = xg[(size_t)(row0 + r) * 32 + c4];
            *(float4*)&sx[r * SXS + c4 * 4] = v;
        }
    }
    __syncthreads();

    bool isR = warp >= 4;
    const float* sW = sm + (isR ? SM_WR : SM_WL);
    float* gout = isR ? g_xr : g_xl;
    int rb = (warp & 3) * 16;   // warp's first row within tile

    float d[8][4];
#pragma unroll
    for (int t = 0; t < 8; t++)
#pragma unroll
        for (int q = 0; q < 4; q++) d[t][q] = 0.f;

#pragma unroll 1
    for (int k0 = 0; k0 < DIN; k0 += 8) {
        // B fragments: load fp32, split hi/lo on the fly
        unsigned bh[8][2], bl[8][2];
        const float* p0 = sW + (k0 + ctid) * SWS + grp;
        const float* p1 = sW + (k0 + ctid + 4) * SWS + grp;
#pragma unroll
        for (int t = 0; t < 8; t++) {
            float f0 = p0[8 * t], f1 = p1[8 * t];
            unsigned h0 = f2tf(f0), h1 = f2tf(f1);
            bh[t][0] = h0; bh[t][1] = h1;
            bl[t][0] = f2tf(f0 - __uint_as_float(h0));
            bl[t][1] = f2tf(f1 - __uint_as_float(h1));
        }
        // A fragment (one m16 slab)
        float f0 = sx[(rb + grp)     * SXS + k0 + ctid];
        float f1 = sx[(rb + grp + 8) * SXS + k0 + ctid];
        float f2 = sx[(rb + grp)     * SXS + k0 + ctid + 4];
        float f3 = sx[(rb + grp + 8) * SXS + k0 + ctid + 4];
        unsigned a0 = f2tf(f0), a1 = f2tf(f1), a2 = f2tf(f2), a3 = f2tf(f3);
        unsigned l0 = f2tf(f0 - __uint_as_float(a0));
        unsigned l1 = f2tf(f1 - __uint_as_float(a1));
        unsigned l2 = f2tf(f2 - __uint_as_float(a2));
        unsigned l3 = f2tf(f3 - __uint_as_float(a3));
#pragma unroll
        for (int t = 0; t < 8; t++) {
            mma_tf32(d[t], a0, a1, a2, a3, bh[t][0], bh[t][1]);
            mma_tf32(d[t], l0, l1, l2, l3, bh[t][0], bh[t][1]);
            mma_tf32(d[t], a0, a1, a2, a3, bl[t][0], bl[t][1]);
        }
    }

    // --- store D ---
    {
        int r0 = row0 + rb + grp;
        int r1 = r0 + 8;
#pragma unroll
        for (int t = 0; t < 8; t++) {
            int col = 8 * t + 2 * ctid;
            if (r0 < NN)
                *(float2*)&gout[(size_t)r0 * DOUT + col] =
                    make_float2(d[t][0], d[t][1]);
            if (r1 < NN)
                *(float2*)&gout[(size_t)r1 * DOUT + col] =
                    make_float2(d[t][2], d[t][3]);
        }
    }
}

// ---------------- 4: FUSED edge pass: logit -> exp -> denom -> scatter -------
// One warp per edge, R3-proven gather layout (lane owns dims 2l,2l+1).
// After the xor-reduce every lane holds v; each lane scatters its own
// ex*xl float2 via red.global.add.v2 (coalesced 256B per warp).
__global__ void __launch_bounds__(256)
k_edge(const int* __restrict__ ei, const float* __restrict__ ea,
       const float* __restrict__ We, const float* __restrict__ att,
       float* __restrict__ out) {
    __shared__ float sWe[DEDGE * DOUT];   // row-major, read as float2
    __shared__ float sAtt[DOUT];
    for (int i = threadIdx.x; i < DEDGE * DOUT; i += 256) sWe[i] = We[i];
    if (threadIdx.x < DOUT) sAtt[threadIdx.x] = att[threadIdx.x];
    __syncthreads();

    int widx = (int)((blockIdx.x * blockDim.x + threadIdx.x) >> 5);
    int lane = threadIdx.x & 31;
    if (widx >= ET) return;

    int src, dst;
    const float* a;
    if (widx < EE) {
        src = __ldg(&ei[widx]);
        dst = __ldg(&ei[EE + widx]);
        a = ea + (size_t)widx * DEDGE;
    } else {
        src = dst = widx - EE;
        a = (const float*)(g_la4 + (size_t)(widx - EE) * 3);
    }

    float av = (lane < DEDGE) ? a[lane] : 0.0f;

    const float2* sWe2 = (const float2*)sWe;
    float e0 = 0.0f, e1 = 0.0f;
#pragma unroll
    for (int k = 0; k < DEDGE; k++) {
        float ak = __shfl_sync(0xFFFFFFFFu, av, k);
        float2 w = sWe2[k * 32 + lane];
        e0 = fmaf(ak, w.x, e0);
        e1 = fmaf(ak, w.y, e1);
    }

    float2 xlv = ((const float2*)g_xl)[(size_t)src * 32 + lane];
    float2 xrv = ((const float2*)g_xr)[(size_t)dst * 32 + lane];
    float m0 = xlv.x + xrv.x + e0;  m0 = (m0 >= 0.0f) ? m0 : 0.2f * m0;
    float m1 = xlv.y + xrv.y + e1;  m1 = (m1 >= 0.0f) ? m1 : 0.2f * m1;

    const float2* sAtt2 = (const float2*)sAtt;
    float2 at = sAtt2[lane];
    float v = m0 * at.x + m1 * at.y;
#pragma unroll
    for (int o = 16; o > 0; o >>= 1) v += __shfl_xor_sync(0xFFFFFFFFu, v, o);

    float ex = __expf(v);            // no max subtraction needed (|v| small)

    if (lane == 0) atomicAdd(&g_denom[dst], ex);

    float wx = ex * xlv.x, wy = ex * xlv.y;
    float* p = out + (size_t)dst * DOUT + 2 * lane;
    unsigned long long gp = (unsigned long long)__cvta_generic_to_global(p);
    asm volatile("red.global.add.v2.f32 [%0], {%1,%2};"
                 :: "l"(gp), "f"(wx), "f"(wy)
                 : "memory");
}

// ---------------- 5: final divide by softmax denominator ---------------------
__global__ void k_final(float* __restrict__ out) {
    int i = blockIdx.x * blockDim.x + threadIdx.x;
    if (i >= NN * DOUT) return;
    out[i] = out[i] / g_denom[i >> 6];
}

// ---------------- launch -----------------------------------------------------
extern "C" void kernel_launch(void* const* d_in, const int* in_sizes, int n_in,
                              void* d_out, int out_size) {
    const float* x   = (const float*)d_in[0];
    const int*   ei  = (const int*)  d_in[1];
    const float* ea  = (const float*)d_in[2];
    const float* Wl  = (const float*)d_in[3];
    const float* Wr  = (const float*)d_in[4];
    const float* We  = (const float*)d_in[5];
    const float* att = (const float*)d_in[6];
    float* out = (float*)d_out;

    cudaFuncSetAttribute(k_gemm, cudaFuncAttributeMaxDynamicSharedMemorySize,
                         SM_TOT_F * 4);

    k_init <<<(NN * DOUT + 255) / 256, 256>>>(out);
    k_deg  <<<(EE + 255) / 256, 256>>>(ei, ea);
    k_norm <<<(NN + 255) / 256, 256>>>();
    k_gemm <<<(NN + TILE_M - 1) / TILE_M, 256, SM_TOT_F * 4>>>(x, Wl, Wr);
    k_edge <<<(ET * 32 + 255) / 256, 256>>>(ei, ea, We, att, out);
    k_final<<<(NN * DOUT + 255) / 256, 256>>>(out);
}

// round 9
// speedup vs baseline: 1.3262x; 1.0786x over previous
#include <cuda_runtime.h>
#include <cstdint>

#define NN     100000
#define EE     1000000
#define DIN    128
#define DOUT   64
#define DEDGE  11
#define ET     (EE + NN)

// ---------------- scratch (device globals) ----------------------------------
__device__ float g_xl[NN * DOUT];          // x @ W_l   (25.6 MB)
__device__ float g_xr[NN * DOUT];          // x @ W_r   (25.6 MB)
__device__ int   g_cnt[NN];                // in-degree
__device__ int   g_off[NN];                // CSR offsets (exclusive scan)
__device__ int   g_cur[NN];                // fill cursors
__device__ int2  g_csr[EE];                // (edge_id, src) grouped by dst

// ---------------- 0: zero counters ------------------------------------------
__global__ void k_zero() {
    int i = blockIdx.x * blockDim.x + threadIdx.x;
    if (i < NN) g_cnt[i] = 0;
}

// ---------------- 1: in-degree histogram -------------------------------------
__global__ void k_count(const int* __restrict__ ei) {
    int e = blockIdx.x * blockDim.x + threadIdx.x;
    if (e >= EE) return;
    atomicAdd(&g_cnt[__ldg(&ei[EE + e])], 1);
}

// ---------------- 2: exclusive prefix scan (single block) --------------------
__global__ void k_scan() {
    __shared__ int warp_sums[32];
    __shared__ int s_carry, s_total;
    int tid = threadIdx.x;
    int lane = tid & 31, wid = tid >> 5;
    if (tid == 0) s_carry = 0;
    __syncthreads();
    for (int base = 0; base < NN; base += 1024) {
        int i = base + tid;
        int v = (i < NN) ? g_cnt[i] : 0;
        int incl = v;
#pragma unroll
        for (int o = 1; o < 32; o <<= 1) {
            int t = __shfl_up_sync(0xFFFFFFFFu, incl, o);
            if (lane >= o) incl += t;
        }
        if (lane == 31) warp_sums[wid] = incl;
        __syncthreads();
        if (wid == 0) {
            int ws = warp_sums[lane];
            int wincl = ws;
#pragma unroll
            for (int o = 1; o < 32; o <<= 1) {
                int t = __shfl_up_sync(0xFFFFFFFFu, wincl, o);
                if (lane >= o) wincl += t;
            }
            warp_sums[lane] = wincl - ws;       // exclusive warp offset
            if (lane == 31) s_total = wincl;    // chunk total
        }
        __syncthreads();
        int excl = incl - v + warp_sums[wid] + s_carry;
        if (i < NN) { g_off[i] = excl; g_cur[i] = excl; }
        __syncthreads();
        if (tid == 0) s_carry += s_total;
        __syncthreads();
    }
}

// ---------------- 3: CSR fill -------------------------------------------------
__global__ void k_fill(const int* __restrict__ ei) {
    int e = blockIdx.x * blockDim.x + threadIdx.x;
    if (e >= EE) return;
    int src = __ldg(&ei[e]);
    int dst = __ldg(&ei[EE + e]);
    int pos = atomicAdd(&g_cur[dst], 1);
    g_csr[pos] = make_int2(e, src);
}

// ---------------- 4: tensor-core dual GEMM (3xTF32) — unchanged from R8 ------
#define SXS   132
#define SWS   72
#define SM_X   0
#define SM_WL  (SM_X + 64 * SXS)            // 8448
#define SM_WR  (SM_WL + 128 * SWS)          // 17664
#define SM_TOT_F (SM_WR + 128 * SWS)        // 26880 floats = 107520 B
#define TILE_M 64

__device__ __forceinline__ unsigned f2tf(float f) {
    unsigned u;
    asm("cvt.rna.tf32.f32 %0, %1;" : "=r"(u) : "f"(f));
    return u;
}
__device__ __forceinline__ void mma_tf32(float* d, unsigned a0, unsigned a1,
                                         unsigned a2, unsigned a3,
                                         unsigned b0, unsigned b1) {
    asm volatile(
        "mma.sync.aligned.m16n8k8.row.col.f32.tf32.tf32.f32 "
        "{%0,%1,%2,%3}, {%4,%5,%6,%7}, {%8,%9}, {%0,%1,%2,%3};"
        : "+f"(d[0]), "+f"(d[1]), "+f"(d[2]), "+f"(d[3])
        : "r"(a0), "r"(a1), "r"(a2), "r"(a3), "r"(b0), "r"(b1));
}

__global__ void __launch_bounds__(256, 2)
k_gemm(const float* __restrict__ x, const float* __restrict__ Wl,
       const float* __restrict__ Wr) {
    extern __shared__ float sm[];
    float* sx = sm + SM_X;

    int tid  = threadIdx.x;
    int warp = tid >> 5;
    int lane = tid & 31;
    int grp  = lane >> 2;
    int ctid = lane & 3;

    for (int i = tid; i < (DIN * DOUT) / 4; i += 256) {
        int k = i >> 4, n4 = i & 15;
        float4 vl = __ldg((const float4*)Wl + i);
        float4 vr = __ldg((const float4*)Wr + i);
        *(float4*)&sm[SM_WL + k * SWS + n4 * 4] = vl;
        *(float4*)&sm[SM_WR + k * SWS + n4 * 4] = vr;
    }

    int row0 = blockIdx.x * TILE_M;
    {
        const float4* xg = (const float4*)x;
        for (int i = tid; i < TILE_M * 32; i += 256) {
            int r = i >> 5, c4 = i & 31;
            float4 v = make_float4(0.f, 0.f, 0.f, 0.f);
            if (row0 + r < NN) v = xg[(size_t)(row0 + r) * 32 + c4];
            *(float4*)&sx[r * SXS + c4 * 4] = v;
        }
    }
    __syncthreads();

    bool isR = warp >= 4;
    const float* sW = sm + (isR ? SM_WR : SM_WL);
    float* gout = isR ? g_xr : g_xl;
    int rb = (warp & 3) * 16;

    float d[8][4];
#pragma unroll
    for (int t = 0; t < 8; t++)
#pragma unroll
        for (int q = 0; q < 4; q++) d[t][q] = 0.f;

#pragma unroll 1
    for (int k0 = 0; k0 < DIN; k0 += 8) {
        unsigned bh[8][2], bl[8][2];
        const float* p0 = sW + (k0 + ctid) * SWS + grp;
        const float* p1 = sW + (k0 + ctid + 4) * SWS + grp;
#pragma unroll
        for (int t = 0; t < 8; t++) {
            float f0 = p0[8 * t], f1 = p1[8 * t];
            unsigned h0 = f2tf(f0), h1 = f2tf(f1);
            bh[t][0] = h0; bh[t][1] = h1;
            bl[t][0] = f2tf(f0 - __uint_as_float(h0));
            bl[t][1] = f2tf(f1 - __uint_as_float(h1));
        }
        float f0 = sx[(rb + grp)     * SXS + k0 + ctid];
        float f1 = sx[(rb + grp + 8) * SXS + k0 + ctid];
        float f2 = sx[(rb + grp)     * SXS + k0 + ctid + 4];
        float f3 = sx[(rb + grp + 8) * SXS + k0 + ctid + 4];
        unsigned a0 = f2tf(f0), a1 = f2tf(f1), a2 = f2tf(f2), a3 = f2tf(f3);
        unsigned l0 = f2tf(f0 - __uint_as_float(a0));
        unsigned l1 = f2tf(f1 - __uint_as_float(a1));
        unsigned l2 = f2tf(f2 - __uint_as_float(a2));
        unsigned l3 = f2tf(f3 - __uint_as_float(a3));
#pragma unroll
        for (int t = 0; t < 8; t++) {
            mma_tf32(d[t], a0, a1, a2, a3, bh[t][0], bh[t][1]);
            mma_tf32(d[t], l0, l1, l2, l3, bh[t][0], bh[t][1]);
            mma_tf32(d[t], a0, a1, a2, a3, bl[t][0], bl[t][1]);
        }
    }

    {
        int r0 = row0 + rb + grp;
        int r1 = r0 + 8;
#pragma unroll
        for (int t = 0; t < 8; t++) {
            int col = 8 * t + 2 * ctid;
            if (r0 < NN)
                *(float2*)&gout[(size_t)r0 * DOUT + col] =
                    make_float2(d[t][0], d[t][1]);
            if (r1 < NN)
                *(float2*)&gout[(size_t)r1 * DOUT + col] =
                    make_float2(d[t][2], d[t][3]);
        }
    }
}

// ---------------- 5: CSR aggregation: one warp per destination ---------------
// Single pass per dst: for each in-edge compute e-term, logit, ex=exp(v)
// (no-max softmax, validated), accumulate ex*xl[src] and denom in registers,
// plus attr_sum for the self-loop mean. Then handle the self-loop and write
// out = acc/denom with ONE coalesced store. Zero atomics.
__global__ void __launch_bounds__(256)
k_aggr(const float* __restrict__ ea, const float* __restrict__ We,
       const float* __restrict__ att, float* __restrict__ out) {
    __shared__ float sWe[DEDGE * DOUT];
    __shared__ float sAtt[DOUT];
    for (int i = threadIdx.x; i < DEDGE * DOUT; i += 256) sWe[i] = We[i];
    if (threadIdx.x < DOUT) sAtt[threadIdx.x] = att[threadIdx.x];
    __syncthreads();

    int dst  = (int)((blockIdx.x * blockDim.x + threadIdx.x) >> 5);
    int lane = threadIdx.x & 31;
    if (dst >= NN) return;

    const float2* sWe2  = (const float2*)sWe;
    const float2* sAtt2 = (const float2*)sAtt;
    float2 at = sAtt2[lane];

    float2 xrv = ((const float2*)g_xr)[(size_t)dst * 32 + lane];

    int start = g_off[dst];
    int deg   = g_cnt[dst];

    float2 acc = make_float2(0.f, 0.f);
    float den = 0.f;
    float attr_sum = 0.f;   // lanes 0..10 hold per-dim attr sums

    for (int j = 0; j < deg; j++) {
        int2 es = __ldg(&g_csr[start + j]);
        int e = es.x, src = es.y;

        float av = (lane < DEDGE) ? __ldg(&ea[(size_t)e * DEDGE + lane]) : 0.f;
        attr_sum += av;

        float e0 = 0.f, e1 = 0.f;
#pragma unroll
        for (int k = 0; k < DEDGE; k++) {
            float ak = __shfl_sync(0xFFFFFFFFu, av, k);
            float2 w = sWe2[k * 32 + lane];
            e0 = fmaf(ak, w.x, e0);
            e1 = fmaf(ak, w.y, e1);
        }

        float2 xlv = ((const float2*)g_xl)[(size_t)src * 32 + lane];
        float m0 = xlv.x + xrv.x + e0;  m0 = (m0 >= 0.f) ? m0 : 0.2f * m0;
        float m1 = xlv.y + xrv.y + e1;  m1 = (m1 >= 0.f) ? m1 : 0.2f * m1;
        float v = m0 * at.x + m1 * at.y;
#pragma unroll
        for (int o = 16; o > 0; o >>= 1)
            v += __shfl_xor_sync(0xFFFFFFFFu, v, o);

        float ex = __expf(v);       // identical on all lanes
        den += ex;
        acc.x = fmaf(ex, xlv.x, acc.x);
        acc.y = fmaf(ex, xlv.y, acc.y);
    }

    // --- self-loop: attr = mean of incoming attrs ---
    {
        float inv = 1.0f / fmaxf((float)deg, 1.0f);
        float av = attr_sum * inv;  // valid on lanes 0..10

        float e0 = 0.f, e1 = 0.f;
#pragma unroll
        for (int k = 0; k < DEDGE; k++) {
            float ak = __shfl_sync(0xFFFFFFFFu, av, k);
            float2 w = sWe2[k * 32 + lane];
            e0 = fmaf(ak, w.x, e0);
            e1 = fmaf(ak, w.y, e1);
        }

        float2 xlv = ((const float2*)g_xl)[(size_t)dst * 32 + lane];
        float m0 = xlv.x + xrv.x + e0;  m0 = (m0 >= 0.f) ? m0 : 0.2f * m0;
        float m1 = xlv.y + xrv.y + e1;  m1 = (m1 >= 0.f) ? m1 : 0.2f * m1;
        float v = m0 * at.x + m1 * at.y;
#pragma unroll
        for (int o = 16; o > 0; o >>= 1)
            v += __shfl_xor_sync(0xFFFFFFFFu, v, o);

        float ex = __expf(v);
        den += ex;
        acc.x = fmaf(ex, xlv.x, acc.x);
        acc.y = fmaf(ex, xlv.y, acc.y);
    }

    float inv_den = 1.0f / den;
    ((float2*)out)[(size_t)dst * 32 + lane] =
        make_float2(acc.x * inv_den, acc.y * inv_den);
}

// ---------------- launch -----------------------------------------------------
extern "C" void kernel_launch(void* const* d_in, const int* in_sizes, int n_in,
                              void* d_out, int out_size) {
    const float* x   = (const float*)d_in[0];
    const int*   ei  = (const int*)  d_in[1];
    const float* ea  = (const float*)d_in[2];
    const float* Wl  = (const float*)d_in[3];
    const float* Wr  = (const float*)d_in[4];
    const float* We  = (const float*)d_in[5];
    const float* att = (const float*)d_in[6];
    float* out = (float*)d_out;

    cudaFuncSetAttribute(k_gemm, cudaFuncAttributeMaxDynamicSharedMemorySize,
                         SM_TOT_F * 4);

    k_zero <<<(NN + 255) / 256, 256>>>();
    k_count<<<(EE + 255) / 256, 256>>>(ei);
    k_scan <<<1, 1024>>>();
    k_fill <<<(EE + 255) / 256, 256>>>(ei);
    k_gemm <<<(NN + TILE_M - 1) / TILE_M, 256, SM_TOT_F * 4>>>(x, Wl, Wr);
    k_aggr <<<(NN * 32 + 255) / 256, 256>>>(ea, We, att, out);
}

// round 12
// speedup vs baseline: 1.3520x; 1.0195x over previous
#include <cuda_runtime.h>
#include <cstdint>

#define NN     100000
#define EE     1000000
#define DIN    128
#define DOUT   64
#define DEDGE  11
#define ET     (EE + NN)

// ---------------- scratch (device globals) ----------------------------------
__device__ float g_xl[NN * DOUT];          // x @ W_l   (25.6 MB)
__device__ float g_xr[NN * DOUT];          // x @ W_r   (25.6 MB)
__device__ int   g_cnt[NN];                // in-degree
__device__ int   g_off[NN];                // CSR offsets (exclusive scan)
__device__ int   g_cur[NN];                // fill cursors
__device__ int2  g_csr[EE];                // (edge_id, src) grouped by dst

// ---------------- 0: zero counters ------------------------------------------
__global__ void k_zero() {
    int i = blockIdx.x * blockDim.x + threadIdx.x;
    if (i < NN) g_cnt[i] = 0;
}

// ---------------- 1: in-degree histogram -------------------------------------
__global__ void k_count(const int* __restrict__ ei) {
    int e = blockIdx.x * blockDim.x + threadIdx.x;
    if (e >= EE) return;
    atomicAdd(&g_cnt[__ldg(&ei[EE + e])], 1);
}

// ---------------- 2: exclusive prefix scan (single block) --------------------
__global__ void k_scan() {
    __shared__ int warp_sums[32];
    __shared__ int s_carry, s_total;
    int tid = threadIdx.x;
    int lane = tid & 31, wid = tid >> 5;
    if (tid == 0) s_carry = 0;
    __syncthreads();
    for (int base = 0; base < NN; base += 1024) {
        int i = base + tid;
        int v = (i < NN) ? g_cnt[i] : 0;
        int incl = v;
#pragma unroll
        for (int o = 1; o < 32; o <<= 1) {
            int t = __shfl_up_sync(0xFFFFFFFFu, incl, o);
            if (lane >= o) incl += t;
        }
        if (lane == 31) warp_sums[wid] = incl;
        __syncthreads();
        if (wid == 0) {
            int ws = warp_sums[lane];
            int wincl = ws;
#pragma unroll
            for (int o = 1; o < 32; o <<= 1) {
                int t = __shfl_up_sync(0xFFFFFFFFu, wincl, o);
                if (lane >= o) wincl += t;
            }
            warp_sums[lane] = wincl - ws;       // exclusive warp offset
            if (lane == 31) s_total = wincl;    // chunk total
        }
        __syncthreads();
        int excl = incl - v + warp_sums[wid] + s_carry;
        if (i < NN) { g_off[i] = excl; g_cur[i] = excl; }
        __syncthreads();
        if (tid == 0) s_carry += s_total;
        __syncthreads();
    }
}

// ---------------- 3: CSR fill -------------------------------------------------
__global__ void k_fill(const int* __restrict__ ei) {
    int e = blockIdx.x * blockDim.x + threadIdx.x;
    if (e >= EE) return;
    int src = __ldg(&ei[e]);
    int dst = __ldg(&ei[EE + e]);
    int pos = atomicAdd(&g_cur[dst], 1);
    g_csr[pos] = make_int2(e, src);
}

// ---------------- 4: tensor-core GEMM (3xTF32), W pre-split in smem ----------
// One launch per weight matrix (selected by is_l flag -> device symbol, NOT a
// host-passed device-global pointer). Block: 256 thr, M-tile 64, N=64, K=128.
// W converted ONCE per block to tf32 hi/lo in smem -> mainloop B-fragments
// are pure LDS, no cvts. Warp w: row-slab (w&3)*16, n-half w>>2.
// smem: x 64x132 (33.8KB) + Whi 128x72 + Wlo 128x72 (73.7KB) = 107.5KB
//   -> 2 CTAs/SM.
#define SXS   132
#define SWS   72
#define SM_X    0
#define SM_WH  (SM_X + 64 * SXS)            // 8448
#define SM_WLO (SM_WH + 128 * SWS)          // 17664
#define SM_TOT_F (SM_WLO + 128 * SWS)       // 26880 floats = 107520 B
#define TILE_M 64

__device__ __forceinline__ unsigned f2tf(float f) {
    unsigned u;
    asm("cvt.rna.tf32.f32 %0, %1;" : "=r"(u) : "f"(f));
    return u;
}
__device__ __forceinline__ void mma_tf32(float* d, unsigned a0, unsigned a1,
                                         unsigned a2, unsigned a3,
                                         unsigned b0, unsigned b1) {
    asm volatile(
        "mma.sync.aligned.m16n8k8.row.col.f32.tf32.tf32.f32 "
        "{%0,%1,%2,%3}, {%4,%5,%6,%7}, {%8,%9}, {%0,%1,%2,%3};"
        : "+f"(d[0]), "+f"(d[1]), "+f"(d[2]), "+f"(d[3])
        : "r"(a0), "r"(a1), "r"(a2), "r"(a3), "r"(b0), "r"(b1));
}

__global__ void __launch_bounds__(256, 2)
k_gemm(const float* __restrict__ x, const float* __restrict__ W, int is_l) {
    extern __shared__ float sm[];
    float* sx = sm + SM_X;
    float* gout = is_l ? g_xl : g_xr;   // device-side symbol reference (valid)

    int tid  = threadIdx.x;
    int warp = tid >> 5;
    int lane = tid & 31;
    int grp  = lane >> 2;
    int ctid = lane & 3;

    // --- fill W as tf32 hi/lo (once per block, float4-wide) ---
    for (int i = tid; i < (DIN * DOUT) / 4; i += 256) {
        int k = i >> 4, n4 = (i & 15) * 4;
        float4 v = __ldg((const float4*)W + i);
        float4 hi, lo;
        hi.x = __uint_as_float(f2tf(v.x)); lo.x = __uint_as_float(f2tf(v.x - hi.x));
        hi.y = __uint_as_float(f2tf(v.y)); lo.y = __uint_as_float(f2tf(v.y - hi.y));
        hi.z = __uint_as_float(f2tf(v.z)); lo.z = __uint_as_float(f2tf(v.z - hi.z));
        hi.w = __uint_as_float(f2tf(v.w)); lo.w = __uint_as_float(f2tf(v.w - hi.w));
        *(float4*)&sm[SM_WH  + k * SWS + n4] = hi;
        *(float4*)&sm[SM_WLO + k * SWS + n4] = lo;
    }

    // --- load x tile 64 x 128 (zero-pad OOB rows) ---
    int row0 = blockIdx.x * TILE_M;
    {
        const float4* xg = (const float4*)x;
        for (int i = tid; i < TILE_M * 32; i += 256) {
            int r = i >> 5, c4 = i & 31;
            float4 v = make_float4(0.f, 0.f, 0.f, 0.f);
            if (row0 + r < NN) v = xg[(size_t)(row0 + r) * 32 + c4];
            *(float4*)&sx[r * SXS + c4 * 4] = v;
        }
    }
    __syncthreads();

    int rb = (warp & 3) * 16;      // row slab within tile
    int nh = (warp >> 2) * 32;     // n-half base column

    float d[4][4];
#pragma unroll
    for (int t = 0; t < 4; t++)
#pragma unroll
        for (int q = 0; q < 4; q++) d[t][q] = 0.f;

#pragma unroll 1
    for (int k0 = 0; k0 < DIN; k0 += 8) {
        // B fragments: pure LDS, already tf32
        unsigned bh[4][2], bl[4][2];
        const float* ph0 = sm + SM_WH  + (k0 + ctid) * SWS + nh + grp;
        const float* ph1 = sm + SM_WH  + (k0 + ctid + 4) * SWS + nh + grp;
        const float* pl0 = sm + SM_WLO + (k0 + ctid) * SWS + nh + grp;
        const float* pl1 = sm + SM_WLO + (k0 + ctid + 4) * SWS + nh + grp;
#pragma unroll
        for (int t = 0; t < 4; t++) {
            bh[t][0] = __float_as_uint(ph0[8 * t]);
            bh[t][1] = __float_as_uint(ph1[8 * t]);
            bl[t][0] = __float_as_uint(pl0[8 * t]);
            bl[t][1] = __float_as_uint(pl1[8 * t]);
        }
        // A fragment: cvt on the fly (only 4 values)
        float f0 = sx[(rb + grp)     * SXS + k0 + ctid];
        float f1 = sx[(rb + grp + 8) * SXS + k0 + ctid];
        float f2 = sx[(rb + grp)     * SXS + k0 + ctid + 4];
        float f3 = sx[(rb + grp + 8) * SXS + k0 + ctid + 4];
        unsigned a0 = f2tf(f0), a1 = f2tf(f1), a2 = f2tf(f2), a3 = f2tf(f3);
        unsigned l0 = f2tf(f0 - __uint_as_float(a0));
        unsigned l1 = f2tf(f1 - __uint_as_float(a1));
        unsigned l2 = f2tf(f2 - __uint_as_float(a2));
        unsigned l3 = f2tf(f3 - __uint_as_float(a3));
#pragma unroll
        for (int t = 0; t < 4; t++) {
            mma_tf32(d[t], a0, a1, a2, a3, bh[t][0], bh[t][1]);
            mma_tf32(d[t], l0, l1, l2, l3, bh[t][0], bh[t][1]);
            mma_tf32(d[t], a0, a1, a2, a3, bl[t][0], bl[t][1]);
        }
    }

    {
        int r0 = row0 + rb + grp;
        int r1 = r0 + 8;
#pragma unroll
        for (int t = 0; t < 4; t++) {
            int col = nh + 8 * t + 2 * ctid;
            if (r0 < NN)
                *(float2*)&gout[(size_t)r0 * DOUT + col] =
                    make_float2(d[t][0], d[t][1]);
            if (r1 < NN)
                *(float2*)&gout[(size_t)r1 * DOUT + col] =
                    make_float2(d[t][2], d[t][3]);
        }
    }
}

// ---------------- 5: CSR aggregation, unroll-2 interleaved chains ------------
// One warp per destination. Edge pairs processed with both load chains in
// flight (MLP=2) and shfl chains interleaved. Zero atomics; single store.
__global__ void __launch_bounds__(256)
k_aggr(const float* __restrict__ ea, const float* __restrict__ We,
       const float* __restrict__ att, float* __restrict__ out) {
    __shared__ float sWe[DEDGE * DOUT];
    __shared__ float sAtt[DOUT];
    for (int i = threadIdx.x; i < DEDGE * DOUT; i += 256) sWe[i] = We[i];
    if (threadIdx.x < DOUT) sAtt[threadIdx.x] = att[threadIdx.x];
    __syncthreads();

    int dst  = (int)((blockIdx.x * blockDim.x + threadIdx.x) >> 5);
    int lane = threadIdx.x & 31;
    if (dst >= NN) return;

    const float2* sWe2  = (const float2*)sWe;
    const float2* sAtt2 = (const float2*)sAtt;
    float2 at = sAtt2[lane];

    float2 xrv = ((const float2*)g_xr)[(size_t)dst * 32 + lane];

    int start = g_off[dst];
    int deg   = g_cnt[dst];

    float2 acc = make_float2(0.f, 0.f);
    float den = 0.f;
    float attr_sum = 0.f;   // lanes 0..10 hold per-dim attr sums

    int j = 0;
    for (; j + 2 <= deg; j += 2) {
        int2 es0 = __ldg(&g_csr[start + j]);
        int2 es1 = __ldg(&g_csr[start + j + 1]);
        float av0 = (lane < DEDGE) ? __ldg(&ea[(size_t)es0.x * DEDGE + lane]) : 0.f;
        float av1 = (lane < DEDGE) ? __ldg(&ea[(size_t)es1.x * DEDGE + lane]) : 0.f;
        float2 xlv0 = ((const float2*)g_xl)[(size_t)es0.y * 32 + lane];
        float2 xlv1 = ((const float2*)g_xl)[(size_t)es1.y * 32 + lane];
        attr_sum += av0 + av1;

        float e00 = 0.f, e01 = 0.f, e10 = 0.f, e11 = 0.f;
#pragma unroll
        for (int k = 0; k < DEDGE; k++) {
            float ak0 = __shfl_sync(0xFFFFFFFFu, av0, k);
            float ak1 = __shfl_sync(0xFFFFFFFFu, av1, k);
            float2 w = sWe2[k * 32 + lane];
            e00 = fmaf(ak0, w.x, e00);
            e01 = fmaf(ak0, w.y, e01);
            e10 = fmaf(ak1, w.x, e10);
            e11 = fmaf(ak1, w.y, e11);
        }

        float m00 = xlv0.x + xrv.x + e00;  m00 = (m00 >= 0.f) ? m00 : 0.2f * m00;
        float m01 = xlv0.y + xrv.y + e01;  m01 = (m01 >= 0.f) ? m01 : 0.2f * m01;
        float m10 = xlv1.x + xrv.x + e10;  m10 = (m10 >= 0.f) ? m10 : 0.2f * m10;
        float m11 = xlv1.y + xrv.y + e11;  m11 = (m11 >= 0.f) ? m11 : 0.2f * m11;
        float v0 = m00 * at.x + m01 * at.y;
        float v1 = m10 * at.x + m11 * at.y;
#pragma unroll
        for (int o = 16; o > 0; o >>= 1) {
            v0 += __shfl_xor_sync(0xFFFFFFFFu, v0, o);
            v1 += __shfl_xor_sync(0xFFFFFFFFu, v1, o);
        }

        float ex0 = __expf(v0);
        float ex1 = __expf(v1);
        den += ex0 + ex1;
        acc.x = fmaf(ex0, xlv0.x, fmaf(ex1, xlv1.x, acc.x));
        acc.y = fmaf(ex0, xlv0.y, fmaf(ex1, xlv1.y, acc.y));
    }
    if (j < deg) {
        int2 es = __ldg(&g_csr[start + j]);
        float av = (lane < DEDGE) ? __ldg(&ea[(size_t)es.x * DEDGE + lane]) : 0.f;
        float2 xlv = ((const float2*)g_xl)[(size_t)es.y * 32 + lane];
        attr_sum += av;
        float e0 = 0.f, e1 = 0.f;
#pragma unroll
        for (int k = 0; k < DEDGE; k++) {
            float ak = __shfl_sync(0xFFFFFFFFu, av, k);
            float2 w = sWe2[k * 32 + lane];
            e0 = fmaf(ak, w.x, e0);
            e1 = fmaf(ak, w.y, e1);
        }
        float m0 = xlv.x + xrv.x + e0;  m0 = (m0 >= 0.f) ? m0 : 0.2f * m0;
        float m1 = xlv.y + xrv.y + e1;  m1 = (m1 >= 0.f) ? m1 : 0.2f * m1;
        float v = m0 * at.x + m1 * at.y;
#pragma unroll
        for (int o = 16; o > 0; o >>= 1)
            v += __shfl_xor_sync(0xFFFFFFFFu, v, o);
        float ex = __expf(v);
        den += ex;
        acc.x = fmaf(ex, xlv.x, acc.x);
        acc.y = fmaf(ex, xlv.y, acc.y);
    }

    // --- self-loop: attr = mean of incoming attrs ---
    {
        float inv = 1.0f / fmaxf((float)deg, 1.0f);
        float av = attr_sum * inv;  // valid on lanes 0..10

        float e0 = 0.f, e1 = 0.f;
#pragma unroll
        for (int k = 0; k < DEDGE; k++) {
            float ak = __shfl_sync(0xFFFFFFFFu, av, k);
            float2 w = sWe2[k * 32 + lane];
            e0 = fmaf(ak, w.x, e0);
            e1 = fmaf(ak, w.y, e1);
        }

        float2 xlv = ((const float2*)g_xl)[(size_t)dst * 32 + lane];
        float m0 = xlv.x + xrv.x + e0;  m0 = (m0 >= 0.f) ? m0 : 0.2f * m0;
        float m1 = xlv.y + xrv.y + e1;  m1 = (m1 >= 0.f) ? m1 : 0.2f * m1;
        float v = m0 * at.x + m1 * at.y;
#pragma unroll
        for (int o = 16; o > 0; o >>= 1)
            v += __shfl_xor_sync(0xFFFFFFFFu, v, o);

        float ex = __expf(v);
        den += ex;
        acc.x = fmaf(ex, xlv.x, acc.x);
        acc.y = fmaf(ex, xlv.y, acc.y);
    }

    float inv_den = 1.0f / den;
    ((float2*)out)[(size_t)dst * 32 + lane] =
        make_float2(acc.x * inv_den, acc.y * inv_den);
}

// ---------------- launch -----------------------------------------------------
extern "C" void kernel_launch(void* const* d_in, const int* in_sizes, int n_in,
                              void* d_out, int out_size) {
    const float* x   = (const float*)d_in[0];
    const int*   ei  = (const int*)  d_in[1];
    const float* ea  = (const float*)d_in[2];
    const float* Wl  = (const float*)d_in[3];
    const float* Wr  = (const float*)d_in[4];
    const float* We  = (const float*)d_in[5];
    const float* att = (const float*)d_in[6];
    float* out = (float*)d_out;

    cudaFuncSetAttribute(k_gemm, cudaFuncAttributeMaxDynamicSharedMemorySize,
                         SM_TOT_F * 4);

    k_zero <<<(NN + 255) / 256, 256>>>();
    k_count<<<(EE + 255) / 256, 256>>>(ei);
    k_scan <<<1, 1024>>>();
    k_fill <<<(EE + 255) / 256, 256>>>(ei);
    int nblk = (NN + TILE_M - 1) / TILE_M;
    k_gemm <<<nblk, 256, SM_TOT_F * 4>>>(x, Wl, 1);
    k_gemm <<<nblk, 256, SM_TOT_F * 4>>>(x, Wr, 0);
    k_aggr <<<(NN * 32 + 255) / 256, 256>>>(ea, We, att, out);
}